// round 4
// baseline (speedup 1.0000x reference)
#include <cuda_runtime.h>
#include <cstdint>

// out[100000,128] = x[100000,128] @ (Wc+Wn)[128,128] + b[128]
// (gamma/segment-sum in the reference is dead code; edge_index unused)
//
// tf32 mma.sync (m16n8k8). CTA: 128 rows x 128 cols, 8 warps of 32x64.
// x staged in smem (conflict-free stride-132); W read from L1-resident global.
//
// Inputs: d_in[0]=x f32 [100000,128], d_in[1]=edge_index i64 (UNUSED),
//         d_in[2]=Wc f32 [128,128], d_in[3]=Wn f32 [128,128], d_in[4]=b f32 [128]

#define D 128
#define TILE_M 128
#define XS_STRIDE 132   // floats; bank = 4*row_group + t4 -> conflict-free

// W^T, tf32-rounded: g_Wt[n*128 + k] = tf32(Wc[k][n] + Wn[k][n])
__device__ float g_Wt[D * D];

__device__ __forceinline__ float to_tf32(float f) {
    float r;
    asm("cvt.rna.tf32.f32 %0, %1;" : "=f"(r) : "f"(f));
    return r;
}

__global__ void prep_w_kernel(const float* __restrict__ Wc,
                              const float* __restrict__ Wn) {
    int i = blockIdx.x * blockDim.x + threadIdx.x;
    if (i >= D * D) return;
    int n = i >> 7, k = i & 127;
    g_Wt[n * D + k] = to_tf32(Wc[k * D + n] + Wn[k * D + n]);
}

#define MMA_TF32(c, a0, a1, a2, a3, b0, b1)                                   \
    asm volatile(                                                             \
        "mma.sync.aligned.m16n8k8.row.col.f32.tf32.tf32.f32 "                 \
        "{%0,%1,%2,%3}, {%4,%5,%6,%7}, {%8,%9}, {%0,%1,%2,%3};"               \
        : "+f"((c)[0]), "+f"((c)[1]), "+f"((c)[2]), "+f"((c)[3])              \
        : "r"(a0), "r"(a1), "r"(a2), "r"(a3), "r"(b0), "r"(b1))

__global__ __launch_bounds__(256, 2)
void gemm_tf32_kernel(const float* __restrict__ x,
                      const float* __restrict__ bias,
                      float* __restrict__ out, int nrows) {
    extern __shared__ float xs[];              // [128][132]

    const int tid = threadIdx.x;
    const int lane = tid & 31;
    const int wid = tid >> 5;
    const int g = lane >> 2;       // 0..7
    const int t4 = lane & 3;       // 0..3
    const int wm = wid >> 1;       // 0..3  (32 rows each)
    const int wn = wid & 1;        // 0..1  (64 cols each)
    const int row0 = blockIdx.x * TILE_M;

    // ---- load x tile, tf32-round, into smem (stride 132) ----
#pragma unroll
    for (int it = 0; it < 16; it++) {
        int idx = tid + 256 * it;          // 0..4095 float4s
        int r = idx >> 5, j = idx & 31;
        int grow = row0 + r;
        float4 v = make_float4(0.f, 0.f, 0.f, 0.f);
        if (grow < nrows) v = *(const float4*)(x + (size_t)grow * D + 4 * j);
        v.x = to_tf32(v.x); v.y = to_tf32(v.y);
        v.z = to_tf32(v.z); v.w = to_tf32(v.w);
        *(float4*)(xs + r * XS_STRIDE + 4 * j) = v;
    }
    __syncthreads();

    // ---- compute: warp tile 32x64, m16n8k8, 16 k-steps ----
    float acc[2][8][4];
#pragma unroll
    for (int i = 0; i < 2; i++)
#pragma unroll
        for (int j = 0; j < 8; j++)
#pragma unroll
            for (int q = 0; q < 4; q++) acc[i][j][q] = 0.0f;

    const uint32_t* xa = (const uint32_t*)(xs + (wm * 32 + g) * XS_STRIDE + t4);
    // B fragments from global W^T (L1-resident, 64KB)
    const uint32_t* wb = (const uint32_t*)(g_Wt + (wn * 64 + g) * D + t4);

#pragma unroll 2
    for (int s = 0; s < 16; s++) {
        const int k8 = 8 * s;
        uint32_t b[8][2];
#pragma unroll
        for (int j = 0; j < 8; j++) {
            b[j][0] = wb[j * 8 * D + k8];
            b[j][1] = wb[j * 8 * D + k8 + 4];
        }
        uint32_t a[2][4];
#pragma unroll
        for (int i = 0; i < 2; i++) {
            a[i][0] = xa[i * 16 * XS_STRIDE + k8];
            a[i][1] = xa[i * 16 * XS_STRIDE + 8 * XS_STRIDE + k8];
            a[i][2] = xa[i * 16 * XS_STRIDE + k8 + 4];
            a[i][3] = xa[i * 16 * XS_STRIDE + 8 * XS_STRIDE + k8 + 4];
        }
#pragma unroll
        for (int i = 0; i < 2; i++)
#pragma unroll
            for (int j = 0; j < 8; j++)
                MMA_TF32(acc[i][j], a[i][0], a[i][1], a[i][2], a[i][3],
                         b[j][0], b[j][1]);
    }

    // ---- epilogue: bias + store directly from accumulators ----
    // m16n8 acc layout: c0,c1 at (row=g, col=2*t4, 2*t4+1); c2,c3 at row=g+8.
#pragma unroll
    for (int j = 0; j < 8; j++) {
        int col = wn * 64 + 8 * j + 2 * t4;
        float b0 = __ldg(bias + col), b1 = __ldg(bias + col + 1);
#pragma unroll
        for (int i = 0; i < 2; i++) {
            int r_lo = row0 + wm * 32 + 16 * i + g;
            int r_hi = r_lo + 8;
            if (r_lo < nrows) {
                float2 v = make_float2(acc[i][j][0] + b0, acc[i][j][1] + b1);
                *(float2*)(out + (size_t)r_lo * D + col) = v;
            }
            if (r_hi < nrows) {
                float2 v = make_float2(acc[i][j][2] + b0, acc[i][j][3] + b1);
                *(float2*)(out + (size_t)r_hi * D + col) = v;
            }
        }
    }
}

extern "C" void kernel_launch(void* const* d_in, const int* in_sizes, int n_in,
                              void* d_out, int out_size) {
    const float* x    = (const float*)d_in[0];
    const float* Wc   = (const float*)d_in[2];
    const float* Wn   = (const float*)d_in[3];
    const float* bias = (const float*)d_in[4];
    float* out = (float*)d_out;

    const int nrows = in_sizes[0] / D;  // 100000

    prep_w_kernel<<<(D * D + 255) / 256, 256>>>(Wc, Wn);

    const int smem_bytes = TILE_M * XS_STRIDE * 4;   // 67,584
    cudaFuncSetAttribute(gemm_tf32_kernel,
                         cudaFuncAttributeMaxDynamicSharedMemorySize, smem_bytes);

    int grid = (nrows + TILE_M - 1) / TILE_M;  // 782
    gemm_tf32_kernel<<<grid, 256, smem_bytes>>>(x, bias, out, nrows);
}

// round 5
// speedup vs baseline: 2.1527x; 2.1527x over previous
#include <cuda_runtime.h>
#include <cstdint>

// out[100000,128] = x[100000,128] @ (Wc+Wn)[128,128] + b[128]
// (gamma/segment-sum in the reference is dead code; edge_index unused)
//
// tf32 mma.sync (m16n8k8), cp.async double-buffered K-chunks (K=32 x 4).
// CTA: 128 rows x 128 cols, 8 warps of 32x64, 2 CTAs/SM.
//
// Inputs: d_in[0]=x f32 [100000,128], d_in[1]=edge_index i64 (UNUSED),
//         d_in[2]=Wc f32 [128,128], d_in[3]=Wn f32 [128,128], d_in[4]=b f32 [128]

#define D 128
#define TILE_M 128
#define KC 32            // K-chunk
#define NCHUNK 4
#define CS 36            // chunk row stride in floats (36 mod 32 = 4 -> conflict-free)

// W^T, tf32(RNA)-rounded: g_Wt[n*128 + k] = tf32(Wc[k][n] + Wn[k][n])
__device__ float g_Wt[D * D];

__device__ __forceinline__ float to_tf32(float f) {
    float r;
    asm("cvt.rna.tf32.f32 %0, %1;" : "=f"(r) : "f"(f));
    return r;
}

__global__ void prep_w_kernel(const float* __restrict__ Wc,
                              const float* __restrict__ Wn) {
    int i = blockIdx.x * blockDim.x + threadIdx.x;
    if (i >= D * D) return;
    int n = i >> 7, k = i & 127;
    g_Wt[n * D + k] = to_tf32(Wc[k * D + n] + Wn[k * D + n]);
}

#define MMA_TF32(c, a0, a1, a2, a3, b0, b1)                                   \
    asm volatile(                                                             \
        "mma.sync.aligned.m16n8k8.row.col.f32.tf32.tf32.f32 "                 \
        "{%0,%1,%2,%3}, {%4,%5,%6,%7}, {%8,%9}, {%0,%1,%2,%3};"               \
        : "+f"((c)[0]), "+f"((c)[1]), "+f"((c)[2]), "+f"((c)[3])              \
        : "r"(a0), "r"(a1), "r"(a2), "r"(a3), "r"(b0), "r"(b1))

__device__ __forceinline__ void cp_async16(uint32_t dst, const void* src, int valid) {
    asm volatile("cp.async.cg.shared.global [%0], [%1], 16, %2;"
                 :: "r"(dst), "l"(src), "r"(valid ? 16 : 0));
}

__global__ __launch_bounds__(256, 2)
void gemm_tf32_kernel(const float* __restrict__ x,
                      const float* __restrict__ bias,
                      float* __restrict__ out, int nrows) {
    // smem: xs[2][128][36], ws[2][128][36]
    extern __shared__ float sm[];
    float* xs = sm;                          // 2 * 4608 floats
    float* ws = sm + 2 * TILE_M * CS;        // 2 * 4608 floats

    const int tid = threadIdx.x;
    const int lane = tid & 31;
    const int wid = tid >> 5;
    const int g = lane >> 2;       // 0..7
    const int t4 = lane & 3;       // 0..3
    const int wm = wid >> 1;       // 0..3  (32 rows each)
    const int wn = wid & 1;        // 0..1  (64 cols each)
    const int row0 = blockIdx.x * TILE_M;

    // per-thread load coords: 4 transfers per matrix per chunk
    const int lr = tid >> 3;           // 0..31 base row (x4 iterations -> 128 rows)
    const int lk = (tid & 7) << 2;     // k offset within chunk: 0,4,...,28

    const uint32_t xs_b = (uint32_t)__cvta_generic_to_shared(xs);
    const uint32_t ws_b = (uint32_t)__cvta_generic_to_shared(ws);

    // ---- issue chunk loads ----
    auto load_chunk = [&](int c, int buf) {
        const int k0 = c * KC;
        uint32_t xd = xs_b + (uint32_t)(buf * TILE_M * CS) * 4;
        uint32_t wd = ws_b + (uint32_t)(buf * TILE_M * CS) * 4;
#pragma unroll
        for (int it = 0; it < 4; it++) {
            int r = lr + 32 * it;
            int grow = row0 + r;
            cp_async16(xd + (uint32_t)(r * CS + lk) * 4,
                       x + (size_t)grow * D + k0 + lk, grow < nrows);
            cp_async16(wd + (uint32_t)(r * CS + lk) * 4,
                       g_Wt + (size_t)r * D + k0 + lk, 1);
        }
        asm volatile("cp.async.commit_group;" ::: "memory");
    };

    float acc[2][8][4];
#pragma unroll
    for (int i = 0; i < 2; i++)
#pragma unroll
        for (int j = 0; j < 8; j++)
#pragma unroll
            for (int q = 0; q < 4; q++) acc[i][j][q] = 0.0f;

    load_chunk(0, 0);

    const float* xa_base = xs + (wm * 32 + g) * CS + t4;
    const float* wb_base = ws + (wn * 64 + g) * CS + t4;

#pragma unroll
    for (int c = 0; c < NCHUNK; c++) {
        const int buf = c & 1;
        if (c + 1 < NCHUNK) {
            load_chunk(c + 1, (c + 1) & 1);
            asm volatile("cp.async.wait_group 1;" ::: "memory");
        } else {
            asm volatile("cp.async.wait_group 0;" ::: "memory");
        }
        __syncthreads();

        const uint32_t* xa = (const uint32_t*)(xa_base + buf * TILE_M * CS);
        const uint32_t* wb = (const uint32_t*)(wb_base + buf * TILE_M * CS);

#pragma unroll
        for (int s = 0; s < 4; s++) {
            const int k8 = 8 * s;
            uint32_t a[2][4];
#pragma unroll
            for (int i = 0; i < 2; i++) {
                a[i][0] = xa[(16 * i) * CS + k8];
                a[i][1] = xa[(16 * i + 8) * CS + k8];
                a[i][2] = xa[(16 * i) * CS + k8 + 4];
                a[i][3] = xa[(16 * i + 8) * CS + k8 + 4];
            }
            uint32_t b[8][2];
#pragma unroll
            for (int j = 0; j < 8; j++) {
                b[j][0] = wb[j * 8 * CS + k8];
                b[j][1] = wb[j * 8 * CS + k8 + 4];
            }
#pragma unroll
            for (int i = 0; i < 2; i++)
#pragma unroll
                for (int j = 0; j < 8; j++)
                    MMA_TF32(acc[i][j], a[i][0], a[i][1], a[i][2], a[i][3],
                             b[j][0], b[j][1]);
        }
        __syncthreads();
    }

    // ---- epilogue: bias + store directly from accumulators ----
#pragma unroll
    for (int j = 0; j < 8; j++) {
        int col = wn * 64 + 8 * j + 2 * t4;
        float b0 = __ldg(bias + col), b1 = __ldg(bias + col + 1);
#pragma unroll
        for (int i = 0; i < 2; i++) {
            int r_lo = row0 + wm * 32 + 16 * i + g;
            int r_hi = r_lo + 8;
            if (r_lo < nrows) {
                float2 v = make_float2(acc[i][j][0] + b0, acc[i][j][1] + b1);
                *(float2*)(out + (size_t)r_lo * D + col) = v;
            }
            if (r_hi < nrows) {
                float2 v = make_float2(acc[i][j][2] + b0, acc[i][j][3] + b1);
                *(float2*)(out + (size_t)r_hi * D + col) = v;
            }
        }
    }
}

extern "C" void kernel_launch(void* const* d_in, const int* in_sizes, int n_in,
                              void* d_out, int out_size) {
    const float* x    = (const float*)d_in[0];
    const float* Wc   = (const float*)d_in[2];
    const float* Wn   = (const float*)d_in[3];
    const float* bias = (const float*)d_in[4];
    float* out = (float*)d_out;

    const int nrows = in_sizes[0] / D;  // 100000

    prep_w_kernel<<<(D * D + 255) / 256, 256>>>(Wc, Wn);

    const int smem_bytes = 4 * TILE_M * CS * 4;   // 73,728 B
    cudaFuncSetAttribute(gemm_tf32_kernel,
                         cudaFuncAttributeMaxDynamicSharedMemorySize, smem_bytes);

    int grid = (nrows + TILE_M - 1) / TILE_M;  // 782
    gemm_tf32_kernel<<<grid, 256, smem_bytes>>>(x, bias, out, nrows);
}